// round 3
// baseline (speedup 1.0000x reference)
#include <cuda_runtime.h>
#include <cuda_fp16.h>
#include <cstdint>
#include <cstddef>

// ---------------- problem constants ----------------
static constexpr int T_TOK = 8192;
static constexpr int HID   = 4096;
static constexpr int NOUT  = 6144;   // Q(4096) + K(1024) + V(1024)
static constexpr int QS    = 4096;
static constexpr int KVS   = 1024;
static constexpr int RANK  = 16;
static constexpr int KEXT  = 384;    // 8 slots * 3 targets * 16 ranks
static constexpr int KTOT  = HID + KEXT;  // 4480
static constexpr int JPER  = 48;     // 3*16 per slot

// ---------------- scratch (static device memory; no allocation) ----------------
__device__ __align__(1024) __half g_xh[(size_t)T_TOK * KTOT];   // 73.4 MB
__device__ __align__(1024) __half g_wh[(size_t)NOUT * KTOT];    // 55.1 MB
__device__ __align__(1024) __half g_ah[(size_t)KEXT * HID];     //  3.1 MB
__device__ __align__(1024) float  g_abuf[(size_t)T_TOK * KEXT]; // 12.6 MB

// ---------------- PTX helpers (base-target only: sm_80+ features) ----------------
__device__ __forceinline__ uint32_t smem_u32(const void* p) {
    uint32_t a;
    asm("{ .reg .u64 t; cvta.to.shared.u64 t, %1; cvt.u32.u64 %0, t; }" : "=r"(a) : "l"(p));
    return a;
}

__device__ __forceinline__ void cp_async16(uint32_t dst, const void* src) {
    asm volatile("cp.async.cg.shared.global [%0], [%1], 16;\n" :: "r"(dst), "l"(src) : "memory");
}

#define CP_COMMIT()  asm volatile("cp.async.commit_group;\n" ::: "memory")
#define CP_WAIT(n)   asm volatile("cp.async.wait_group %0;\n" :: "n"(n) : "memory")

__device__ __forceinline__ uint32_t sw128(uint32_t off) {
    return off ^ ((off >> 3) & 0x70);
}

__device__ __forceinline__ void ldmatrix_x4(uint32_t* r, uint32_t addr) {
    asm volatile("ldmatrix.sync.aligned.m8n8.x4.shared.b16 {%0,%1,%2,%3}, [%4];"
                 : "=r"(r[0]), "=r"(r[1]), "=r"(r[2]), "=r"(r[3]) : "r"(addr));
}

__device__ __forceinline__ void mma16816(float* c, const uint32_t* a, uint32_t b0, uint32_t b1) {
    asm volatile("mma.sync.aligned.m16n8k16.row.col.f32.f16.f16.f32 "
                 "{%0,%1,%2,%3}, {%4,%5,%6,%7}, {%8,%9}, {%0,%1,%2,%3};"
                 : "+f"(c[0]), "+f"(c[1]), "+f"(c[2]), "+f"(c[3])
                 : "r"(a[0]), "r"(a[1]), "r"(a[2]), "r"(a[3]), "r"(b0), "r"(b1));
}

// ---------------- small elementwise kernels ----------------
__device__ __forceinline__ uint4 pack8(float4 a, float4 b) {
    __half2 h0 = __floats2half2_rn(a.x, a.y);
    __half2 h1 = __floats2half2_rn(a.z, a.w);
    __half2 h2 = __floats2half2_rn(b.x, b.y);
    __half2 h3 = __floats2half2_rn(b.z, b.w);
    uint4 u;
    u.x = *reinterpret_cast<uint32_t*>(&h0);
    u.y = *reinterpret_cast<uint32_t*>(&h1);
    u.z = *reinterpret_cast<uint32_t*>(&h2);
    u.w = *reinterpret_cast<uint32_t*>(&h3);
    return u;
}

// converts rows x 4096 fp32 -> fp16 with output leading dim dld
__global__ void cvt8_kernel(const float* __restrict__ src, __half* __restrict__ dst,
                            int rows, int dld) {
    int idx = blockIdx.x * blockDim.x + threadIdx.x;
    const int cols8 = HID / 8;  // 512
    if (idx >= rows * cols8) return;
    int r = idx / cols8, c = idx % cols8;
    const float4* p = reinterpret_cast<const float4*>(src + (size_t)r * HID + (size_t)c * 8);
    float4 f0 = p[0], f1 = p[1];
    *reinterpret_cast<uint4*>(dst + (size_t)r * dld + (size_t)c * 8) = pack8(f0, f1);
}

// fill W extension columns [4096, 4480): section-masked lora_B values
__global__ void fill_wext_kernel(const float* __restrict__ bq, const float* __restrict__ bk,
                                 const float* __restrict__ bv, __half* __restrict__ wh) {
    int idx = blockIdx.x * blockDim.x + threadIdx.x;
    if (idx >= NOUT * KEXT) return;
    int n = idx / KEXT, j = idx % KEXT;
    int s = j / JPER, rem = j % JPER, i = rem / RANK, r = rem % RANK;
    float v = 0.f;
    if (n < QS) {
        if (i == 0) v = bq[((size_t)s * QS + n) * RANK + r];
    } else if (n < QS + KVS) {
        if (i == 1) v = bk[((size_t)s * KVS + (n - QS)) * RANK + r];
    } else {
        if (i == 2) v = bv[((size_t)s * KVS + (n - QS - KVS)) * RANK + r];
    }
    wh[(size_t)n * KTOT + HID + j] = __float2half(v);
}

// x extension: route+scale the down-projection into x' columns [4096, 4480)
__global__ void mask_scale_kernel(const float* __restrict__ a, const int* __restrict__ t2s,
                                  const float* __restrict__ scal, __half* __restrict__ xh) {
    int idx = blockIdx.x * blockDim.x + threadIdx.x;
    if (idx >= T_TOK * KEXT) return;
    int t = idx / KEXT, j = idx % KEXT;
    int slot = t2s[t];
    int s = j / JPER;
    float v = (s == slot) ? scal[slot] * a[(size_t)t * KEXT + j] : 0.f;
    xh[(size_t)t * KTOT + HID + j] = __float2half(v);
}

// ---------------- fp16 GEMM: C[M,N] = A[M,K] @ B[N,K]^T, fp32 accumulate ----------------
// mma.sync.m16n8k16 + ldmatrix + 4-stage cp.async pipeline.
// CTA tile: 128 x BN, K chunk 64 halves (128B rows -> SW128 swizzle, conflict-free).
// 256 threads = 8 warps in 2(M) x 4(N); warp tile 64 x (BN/4).
template<int BN>
__global__ void __launch_bounds__(256, 1)
hgemm_kernel(const __half* __restrict__ A, int lda,
             const __half* __restrict__ B, int ldb,
             float* __restrict__ C, int ldc, int K) {
    extern __shared__ char smem[];
    constexpr int BM = 128, BK = 64;
    constexpr int STAGE_A = BM * BK * 2;          // 16 KB
    constexpr int STAGE_B = BN * BK * 2;
    constexpr int STAGE   = STAGE_A + STAGE_B;
    constexpr int NSTAGE  = 4;
    constexpr int WN   = BN / 4;                  // warp n-extent
    constexpr int MT   = 4;                       // 16-row m-tiles per warp
    constexpr int NTL  = WN / 8;                  // 8-col n-tiles per warp
    constexpr int NPAIR = WN / 16;                // ldmatrix.x4 loads for B per k-step

    const int tid  = threadIdx.x;
    const int wid  = tid >> 5, lane = tid & 31;
    const int wm   = wid & 1, wn = wid >> 1;      // 2 x 4 warp grid
    const int m0   = blockIdx.x * BM;
    const int n0   = blockIdx.y * BN;
    const uint32_t s_base = smem_u32(smem);
    const int NC = K / BK;

    const int lr   = lane & 7;   // row within 8x8 ldmatrix
    const int lsub = lane >> 3;  // which 8x8 matrix this lane's address feeds
    const int g    = lane >> 2;  // mma group row
    const int t    = lane & 3;   // mma thread-in-group

    auto load_stage = [&](int stage, int c) {
        const uint32_t sa = s_base + stage * STAGE;
        const char* gA = (const char*)(A + (size_t)m0 * lda + (size_t)c * BK);
        const char* gB = (const char*)(B + (size_t)n0 * ldb + (size_t)c * BK);
        #pragma unroll
        for (int i = 0; i < BM * 8 / 256; i++) {
            int id = tid + i * 256; int row = id >> 3, cc = id & 7;
            uint32_t off = (uint32_t)(row * 128 + cc * 16);
            cp_async16(sa + sw128(off), gA + (size_t)row * lda * 2 + cc * 16);
        }
        #pragma unroll
        for (int i = 0; i < BN * 8 / 256; i++) {
            int id = tid + i * 256; int row = id >> 3, cc = id & 7;
            uint32_t off = (uint32_t)(row * 128 + cc * 16);
            cp_async16(sa + STAGE_A + sw128(off), gB + (size_t)row * ldb * 2 + cc * 16);
        }
        CP_COMMIT();
    };

    #pragma unroll
    for (int s = 0; s < NSTAGE - 1; s++) load_stage(s, s);   // NC >= 3 always

    float acc[MT][NTL][4];
    #pragma unroll
    for (int mi = 0; mi < MT; mi++)
        #pragma unroll
        for (int ni = 0; ni < NTL; ni++)
            #pragma unroll
            for (int q = 0; q < 4; q++) acc[mi][ni][q] = 0.f;

    for (int c = 0; c < NC; c++) {
        CP_WAIT(NSTAGE - 2);
        __syncthreads();
        if (c + NSTAGE - 1 < NC) load_stage((c + NSTAGE - 1) % NSTAGE, c + NSTAGE - 1);
        else CP_COMMIT();  // keep group count uniform

        const uint32_t sa = s_base + (c % NSTAGE) * STAGE;
        const uint32_t sb = sa + STAGE_A;

        #pragma unroll
        for (int ks = 0; ks < 4; ks++) {
            uint32_t afr[MT][4], bfr[NPAIR][4];
            #pragma unroll
            for (int mi = 0; mi < MT; mi++) {
                // x4: m0 = rows[0:8) k[0:8), m1 = rows[8:16) k[0:8), m2 = rows[0:8) k[8:16), m3 = rows[8:16) k[8:16)
                int row  = wm * 64 + mi * 16 + (lsub & 1) * 8 + lr;
                int colh = ks * 16 + (lsub >> 1) * 8;
                uint32_t off = (uint32_t)(row * 128 + colh * 2);
                ldmatrix_x4(afr[mi], sa + sw128(off));
            }
            #pragma unroll
            for (int pi = 0; pi < NPAIR; pi++) {
                // x4: m0 = ntile(2pi) k[0:8), m1 = ntile(2pi) k[8:16), m2 = ntile(2pi+1) k[0:8), m3 = ntile(2pi+1) k[8:16)
                int row  = wn * WN + pi * 16 + (lsub >> 1) * 8 + lr;
                int colh = ks * 16 + (lsub & 1) * 8;
                uint32_t off = (uint32_t)(row * 128 + colh * 2);
                ldmatrix_x4(bfr[pi], sb + sw128(off));
            }
            #pragma unroll
            for (int mi = 0; mi < MT; mi++)
                #pragma unroll
                for (int ni = 0; ni < NTL; ni++)
                    mma16816(acc[mi][ni], afr[mi],
                             bfr[ni >> 1][(ni & 1) * 2 + 0],
                             bfr[ni >> 1][(ni & 1) * 2 + 1]);
        }
    }

    // register epilogue -> gmem (float2 stores, 8B aligned: col is even)
    #pragma unroll
    for (int mi = 0; mi < MT; mi++) {
        int r0 = m0 + wm * 64 + mi * 16 + g;
        #pragma unroll
        for (int ni = 0; ni < NTL; ni++) {
            int col = n0 + wn * WN + ni * 8 + 2 * t;
            float2 v0 = make_float2(acc[mi][ni][0], acc[mi][ni][1]);
            float2 v1 = make_float2(acc[mi][ni][2], acc[mi][ni][3]);
            *reinterpret_cast<float2*>(C + (size_t)r0 * ldc + col)       = v0;
            *reinterpret_cast<float2*>(C + (size_t)(r0 + 8) * ldc + col) = v1;
        }
    }
}

// ---------------- launch ----------------
extern "C" void kernel_launch(void* const* d_in, const int* in_sizes, int n_in,
                              void* d_out, int out_size) {
    (void)in_sizes; (void)n_in; (void)out_size;
    const float* x   = (const float*)d_in[0];
    const float* W   = (const float*)d_in[1];
    const float* lA  = (const float*)d_in[2];
    const float* bq  = (const float*)d_in[3];
    const float* bk  = (const float*)d_in[4];
    const float* bv  = (const float*)d_in[5];
    const float* sc  = (const float*)d_in[6];
    const int*   t2s = (const int*)d_in[7];
    float* out = (float*)d_out;

    void *xh_p, *wh_p, *ah_p, *ab_p;
    cudaGetSymbolAddress(&xh_p, g_xh);
    cudaGetSymbolAddress(&wh_p, g_wh);
    cudaGetSymbolAddress(&ah_p, g_ah);
    cudaGetSymbolAddress(&ab_p, g_abuf);
    __half* xh = (__half*)xh_p;
    __half* wh = (__half*)wh_p;
    __half* ah = (__half*)ah_p;
    float*  ab = (float*)ab_p;

    constexpr int SMEM128 = 4 * (128 * 64 * 2 + 128 * 64 * 2);  // 131072
    constexpr int SMEM256 = 4 * (128 * 64 * 2 + 256 * 64 * 2);  // 196608
    cudaFuncSetAttribute(hgemm_kernel<128>, cudaFuncAttributeMaxDynamicSharedMemorySize, SMEM128);
    cudaFuncSetAttribute(hgemm_kernel<256>, cudaFuncAttributeMaxDynamicSharedMemorySize, SMEM256);

    // 1) convert inputs to fp16 scratch
    cvt8_kernel<<<(T_TOK * 512 + 255) / 256, 256>>>(x, xh, T_TOK, KTOT);
    cvt8_kernel<<<(KEXT * 512 + 255) / 256, 256>>>(lA, ah, KEXT, HID);
    cvt8_kernel<<<(NOUT * 512 + 255) / 256, 256>>>(W, wh, NOUT, KTOT);
    fill_wext_kernel<<<(NOUT * KEXT + 255) / 256, 256>>>(bq, bk, bv, wh);

    // 2) down-projection GEMM: a[T, 384] = x @ lora_A^T   (K = HID only)
    hgemm_kernel<128><<<dim3(T_TOK / 128, KEXT / 128), 256, SMEM128>>>(
        xh, KTOT, ah, HID, ab, KEXT, HID);

    // 3) route + scale into x' extension columns
    mask_scale_kernel<<<(T_TOK * KEXT + 255) / 256, 256>>>(ab, t2s, sc, xh);

    // 4) main fused GEMM: out[T, 6144] = x'[T, 4480] @ W'[6144, 4480]^T
    hgemm_kernel<256><<<dim3(T_TOK / 128, NOUT / 256), 256, SMEM256>>>(
        xh, KTOT, wh, KTOT, out, NOUT, KTOT);
}